// round 12
// baseline (speedup 1.0000x reference)
#include <cuda_runtime.h>
#include <cuda_fp16.h>
#include <cstdint>

// Problem constants
#define SEQB   4096
#define DIMX   1024
#define NBLK   8
#define BLKD   128
#define NHEAD  12
#define HDIM   64
#define INNER  768
#define QKVROW (NBLK*INNER)        // 6144
#define WELEM  (NBLK*BLKD*INNER)   // 786432
#define SCALE  0.125f

// 128x32-half subtile (8KB), 64B rows, XOR-swizzled at 16B granularity
#define SUB_BYTES 8192
#define SWZ(row, ch) (((row) * 64) + ((((ch) ^ (((row) >> 1) & 3)) << 4)))

// fp32 epilogue stage layout (gemm_f)
#define FROT(row, u) (((row) * 512) + (((((u) + (row)) & 31)) << 4))   // fp32 tile, 64KB

#define QKV_DSM (24*SUB_BYTES + 1024)   // A(32K) Bq(32K) Bk(32K) Bv(32K) st0(32K) st1(32K)
#define F_DSM   (8*SUB_BYTES + 1024)    // 2 stages x (2A + 2B); stage reuses all 64KB

// ---------------- scratch (device globals; allocation is forbidden) ----------------
__device__ __align__(16) __half g_xh [SEQB*DIMX];
__device__ __align__(16) __half g_wqt[WELEM];         // [blk][n=INNER][k=BLKD]
__device__ __align__(16) __half g_wkt[WELEM];
__device__ __align__(16) __half g_wvt[WELEM];
__device__ __align__(16) __half g_wft[WELEM];         // [blk][n=BLKD][k=INNER]
__device__ __align__(16) __half g_q  [SEQB*QKVROW];
__device__ __align__(16) __half g_k  [SEQB*QKVROW];
__device__ __align__(16) __half g_v  [SEQB*QKVROW];
__device__ __align__(16) __half g_att[SEQB*QKVROW];

// ---------------- helpers ----------------
__device__ __forceinline__ void mma_f16(float c[4], const uint32_t a[4],
                                        uint32_t b0, uint32_t b1) {
    asm volatile(
        "mma.sync.aligned.m16n8k16.row.col.f32.f16.f16.f32 "
        "{%0,%1,%2,%3}, {%4,%5,%6,%7}, {%8,%9}, {%0,%1,%2,%3};\n"
        : "+f"(c[0]), "+f"(c[1]), "+f"(c[2]), "+f"(c[3])
        : "r"(a[0]), "r"(a[1]), "r"(a[2]), "r"(a[3]), "r"(b0), "r"(b1));
}

__device__ __forceinline__ void ldsm4(uint32_t r[4], uint32_t addr) {
    asm volatile("ldmatrix.sync.aligned.m8n8.x4.shared.b16 {%0,%1,%2,%3}, [%4];"
                 : "=r"(r[0]), "=r"(r[1]), "=r"(r[2]), "=r"(r[3]) : "r"(addr));
}

__device__ __forceinline__ void stsm4(uint32_t addr, uint32_t v0, uint32_t v1,
                                      uint32_t v2, uint32_t v3) {
    asm volatile("stmatrix.sync.aligned.m8n8.x4.shared.b16 [%0], {%1,%2,%3,%4};"
                 :: "r"(addr), "r"(v0), "r"(v1), "r"(v2), "r"(v3) : "memory");
}

__device__ __forceinline__ void lds128(uint4& v, uint32_t addr) {
    asm volatile("ld.shared.v4.u32 {%0,%1,%2,%3}, [%4];"
                 : "=r"(v.x), "=r"(v.y), "=r"(v.z), "=r"(v.w) : "r"(addr));
}

__device__ __forceinline__ void sts64(uint32_t addr, float a, float b) {
    asm volatile("st.shared.v2.f32 [%0], {%1,%2};" :: "r"(addr), "f"(a), "f"(b) : "memory");
}

__device__ __forceinline__ uint32_t pack_h2(float a, float b) {
    __half2 h = __floats2half2_rn(a, b);
    return *(uint32_t*)&h;
}

__device__ __forceinline__ void cpa16(uint32_t smem_dst, const __half* gmem_src) {
    asm volatile("cp.async.ca.shared.global [%0], [%1], 16;\n" :: "r"(smem_dst), "l"(gmem_src));
}
__device__ __forceinline__ void cp_commit() { asm volatile("cp.async.commit_group;\n"); }
template <int N>
__device__ __forceinline__ void cp_wait() { asm volatile("cp.async.wait_group %0;\n" :: "n"(N)); }

__device__ __forceinline__ void nbar(int id) {
    asm volatile("bar.sync %0, 256;" :: "r"(id) : "memory");
}

__device__ __forceinline__ uint32_t s2u(const void* p) {
    return (uint32_t)__cvta_generic_to_shared(p);
}

// ---------------- prep: x -> half ----------------
__global__ void conv_x_kernel(const float* __restrict__ x) {
    int i = (blockIdx.x * blockDim.x + threadIdx.x) * 4;
    float4 v = *(const float4*)(x + i);
    __half2* o = (__half2*)(g_xh + i);
    o[0] = __floats2half2_rn(v.x, v.y);
    o[1] = __floats2half2_rn(v.z, v.w);
}

// ---------------- prep: transpose weights to [blk][n][k] half ----------------
__global__ void transpose_qkv_kernel(const float* __restrict__ wq,
                                     const float* __restrict__ wk,
                                     const float* __restrict__ wv) {
    __shared__ float tile[32][33];
    const int mat = blockIdx.z >> 3;
    const int blk = blockIdx.z & 7;
    const float* W = (mat == 0) ? wq : (mat == 1) ? wk : wv;
    __half* O      = (mat == 0) ? g_wqt : (mat == 1) ? g_wkt : g_wvt;
    const float* Wb = W + (size_t)blk * BLKD * INNER;   // [k=BLKD][n=INNER]
    __half* Ob      = O + (size_t)blk * BLKD * INNER;   // [n=INNER][k=BLKD]
    int n0 = blockIdx.x * 32, k0 = blockIdx.y * 32;
    int tx = threadIdx.x & 31, ty0 = threadIdx.x >> 5;
#pragma unroll
    for (int p = 0; p < 4; p++) {
        int ty = ty0 + p * 8;
        tile[ty][tx] = Wb[(size_t)(k0 + ty) * INNER + n0 + tx];
    }
    __syncthreads();
#pragma unroll
    for (int p = 0; p < 4; p++) {
        int ty = ty0 + p * 8;
        Ob[(size_t)(n0 + ty) * BLKD + k0 + tx] = __float2half_rn(tile[tx][ty]);
    }
}

__global__ void transpose_f_kernel(const float* __restrict__ wf) {
    __shared__ float tile[32][33];
    const int blk = blockIdx.z;
    const float* Wb = wf + (size_t)blk * INNER * BLKD;    // [k=INNER][n=BLKD]
    __half* Ob      = g_wft + (size_t)blk * INNER * BLKD; // [n=BLKD][k=INNER]
    int n0 = blockIdx.x * 32, k0 = blockIdx.y * 32;
    int tx = threadIdx.x & 31, ty0 = threadIdx.x >> 5;
#pragma unroll
    for (int p = 0; p < 4; p++) {
        int ty = ty0 + p * 8;
        tile[ty][tx] = Wb[(size_t)(k0 + ty) * BLKD + n0 + tx];
    }
    __syncthreads();
#pragma unroll
    for (int p = 0; p < 4; p++) {
        int ty = ty0 + p * 8;
        Ob[(size_t)(n0 + ty) * INNER + k0 + tx] = __float2half_rn(tile[tx][ty]);
    }
}

// ---------------- mma core: warp tile 64(M) x 64(N), CTA 128x128 ------------------
struct FragCtx {
    int a_row[4];
    int b_row[4];
    int ac, bc;
};

__device__ __forceinline__ void frag_init(FragCtx& f, int lane, int wm, int wn) {
#pragma unroll
    for (int mt = 0; mt < 4; mt++)
        f.a_row[mt] = wm * 64 + mt * 16 + (lane & 7) + ((lane >> 3) & 1) * 8;
#pragma unroll
    for (int np = 0; np < 4; np++)
        f.b_row[np] = wn * 64 + np * 16 + (lane & 7) + ((lane >> 4) & 1) * 8;
    f.ac = lane >> 4;
    f.bc = (lane >> 3) & 1;
}

__device__ __forceinline__ void compute_k32(uint32_t ab, uint32_t bb, const FragCtx& f,
                                            float acc[4][8][4]) {
#pragma unroll
    for (int ks = 0; ks < 2; ks++) {
        const int kb = ks * 2;
        uint32_t a[4][4];
#pragma unroll
        for (int mt = 0; mt < 4; mt++)
            ldsm4(a[mt], ab + SWZ(f.a_row[mt], kb + f.ac));
        uint32_t bf[4][4];
#pragma unroll
        for (int np = 0; np < 4; np++)
            ldsm4(bf[np], bb + SWZ(f.b_row[np], kb + f.bc));
#pragma unroll
        for (int mt = 0; mt < 4; mt++) {
#pragma unroll
            for (int np = 0; np < 4; np++) {
                mma_f16(acc[mt][np * 2 + 0], a[mt], bf[np][0], bf[np][1]);
                mma_f16(acc[mt][np * 2 + 1], a[mt], bf[np][2], bf[np][3]);
            }
        }
    }
}

// load one 128x32 subtile with a 128-thread group id stid in [0,128)
__device__ __forceinline__ void load_sub_g(uint32_t dst, const __half* __restrict__ src,
                                           int ld, int stid) {
    const int r0 = stid >> 2, c = stid & 3;
#pragma unroll
    for (int p = 0; p < 4; p++) {
        const int r = r0 + p * 32;
        cpa16(dst + SWZ(r, c), src + (size_t)r * ld + c * 8);
    }
}

// compute-side: stmatrix acc quadrant into its 8KB region (region-local rows)
__device__ __forceinline__ void cw_stage(const float acc[4][8][4], uint32_t region, int lane) {
    const int t4 = lane >> 3, rr = lane & 7;
#pragma unroll
    for (int mt = 0; mt < 4; mt++) {
#pragma unroll
        for (int ntp = 0; ntp < 4; ntp++) {
            int lr = mt * 16 + (t4 & 1) * 8 + rr;
            int u  = ntp * 2 + (t4 >> 1);
            uint32_t v0 = pack_h2(acc[mt][2 * ntp][0],     acc[mt][2 * ntp][1]);
            uint32_t v1 = pack_h2(acc[mt][2 * ntp][2],     acc[mt][2 * ntp][3]);
            uint32_t v2 = pack_h2(acc[mt][2 * ntp + 1][0], acc[mt][2 * ntp + 1][1]);
            uint32_t v3 = pack_h2(acc[mt][2 * ntp + 1][2], acc[mt][2 * ntp + 1][3]);
            stsm4(region + lr * 128 + (((u + lr) & 7) << 4), v0, v1, v2, v3);
        }
    }
}

// service-side: drain one 8KB quadrant region to C
__device__ __forceinline__ void svc_drain(uint32_t region, __half* __restrict__ C, int ldc,
                                          int wm, int wn, int lane) {
#pragma unroll
    for (int p = 0; p < 16; p++) {
        int lr = p * 4 + (lane >> 3);
        int u  = lane & 7;
        uint4 val;
        lds128(val, region + lr * 128 + (((u + lr) & 7) << 4));
        *(uint4*)(C + (size_t)(wm * 64 + lr) * ldc + wn * 64 + u * 8) = val;
    }
}

// ---------------- QKV: warp-specialized. 4 compute + 4 service warps ---------------
// grid (6, 32, 8), 256 threads, 1 CTA/SM (196KB smem, 240 regs).
__global__ void __launch_bounds__(256, 1) gemm_qkv_kernel() {
    extern __shared__ __align__(16) char dsm[];
    char* base = (char*)(((uintptr_t)dsm + 1023) & ~(uintptr_t)1023);
    const uint32_t Asb = s2u(base);
    const uint32_t Bq_s = Asb + 4 * SUB_BYTES;
    const uint32_t Bk_s = Asb + 8 * SUB_BYTES;
    const uint32_t Bv_s = Asb + 12 * SUB_BYTES;
    const uint32_t St0  = Asb + 16 * SUB_BYTES;
    const uint32_t St1  = Asb + 20 * SUB_BYTES;

    const int tid  = threadIdx.x;
    const int lane = tid & 31;
    const int warp = tid >> 5;

    const int blk = blockIdx.z;
    const size_t woff = (size_t)blk * BLKD * INNER + (size_t)blockIdx.x * 128 * BLKD;
    const size_t coff = (size_t)blockIdx.y * 128 * QKVROW + blk * INNER + blockIdx.x * 128;
    const __half* A  = g_xh + (size_t)blockIdx.y * 128 * DIMX + blk * BLKD;
    const __half* Bq = g_wqt + woff;
    const __half* Bk = g_wkt + woff;
    const __half* Bv = g_wvt + woff;
    __half* Cq = g_q + coff;
    __half* Ck = g_k + coff;
    __half* Cv = g_v + coff;

    if (warp >= 4) {
        // ------------- service path: loads + epilogue drains -------------
        const int stid = tid - 128;
        const int s    = warp - 4;          // quadrant id
        const int wm = s & 1, wn = s >> 1;
        const uint32_t reg0 = St0 + (uint32_t)s * SUB_BYTES;
        const uint32_t reg1 = St1 + (uint32_t)s * SUB_BYTES;

        // g1: A + Bq; g2: Bk; g3: Bv
#pragma unroll
        for (int t = 0; t < 4; t++) {
            load_sub_g(Asb + t * SUB_BYTES,  A  + t * 32, DIMX, stid);
            load_sub_g(Bq_s + t * SUB_BYTES, Bq + t * 32, BLKD, stid);
        }
        cp_commit();
#pragma unroll
        for (int t = 0; t < 4; t++)
            load_sub_g(Bk_s + t * SUB_BYTES, Bk + t * 32, BLKD, stid);
        cp_commit();
#pragma unroll
        for (int t = 0; t < 4; t++)
            load_sub_g(Bv_s + t * SUB_BYTES, Bv + t * 32, BLKD, stid);
        cp_commit();

        cp_wait<2>();            // g1 done
        nbar(1);                 // release compute for q
        nbar(2);                 // q staged by compute
        cp_wait<1>();            // g2 done
        nbar(3);                 // release compute for k
        svc_drain(reg0, Cq, QKVROW, wm, wn, lane);   // overlap: compute does mma k
        nbar(4);                 // k staged by compute (and q stage drained)
        cp_wait<0>();            // g3 done
        nbar(5);                 // release compute for v
        svc_drain(reg1, Ck, QKVROW, wm, wn, lane);   // overlap: compute does mma v
        nbar(6);                 // v staged by compute
        svc_drain(reg0, Cv, QKVROW, wm, wn, lane);
    } else {
        // ------------- compute path: ldsm + mma + stmatrix only -------------
        const int wm = warp & 1, wn = warp >> 1;
        const uint32_t reg0 = St0 + (uint32_t)warp * SUB_BYTES;
        const uint32_t reg1 = St1 + (uint32_t)warp * SUB_BYTES;

        FragCtx f;
        frag_init(f, lane, wm, wn);
        float acc[4][8][4];

        nbar(1);                 // A, Bq ready
        // ---- q ----
#pragma unroll
        for (int mt = 0; mt < 4; mt++)
#pragma unroll
            for (int nt = 0; nt < 8; nt++)
#pragma unroll
                for (int e = 0; e < 4; e++) acc[mt][nt][e] = 0.f;
#pragma unroll
        for (int t = 0; t < 4; t++)
            compute_k32(Asb + t * SUB_BYTES, Bq_s + t * SUB_BYTES, f, acc);
        cw_stage(acc, reg0, lane);
        nbar(2);                 // hand q stage to service
        nbar(3);                 // Bk ready
        // ---- k ----
#pragma unroll
        for (int mt = 0; mt < 4; mt++)
#pragma unroll
            for (int nt = 0; nt < 8; nt++)
#pragma unroll
                for (int e = 0; e < 4; e++) acc[mt][nt][e] = 0.f;
#pragma unroll
        for (int t = 0; t < 4; t++)
            compute_k32(Asb + t * SUB_BYTES, Bk_s + t * SUB_BYTES, f, acc);
        cw_stage(acc, reg1, lane);
        nbar(4);                 // hand k stage to service
        nbar(5);                 // Bv ready (and q stage drained)
        // ---- v ----
#pragma unroll
        for (int mt = 0; mt < 4; mt++)
#pragma unroll
            for (int nt = 0; nt < 8; nt++)
#pragma unroll
                for (int e = 0; e < 4; e++) acc[mt][nt][e] = 0.f;
#pragma unroll
        for (int t = 0; t < 4; t++)
            compute_k32(Asb + t * SUB_BYTES, Bv_s + t * SUB_BYTES, f, acc);
        cw_stage(acc, reg0, lane);
        nbar(6);                 // hand v stage to service
    }
}

// ---------------- output projection: K=768 as 12 k64 chunks, 2-stage ring ----------
// grid (32, 8), 128 threads, 64KB smem -> 2 CTAs/SM.
__global__ void __launch_bounds__(128, 2) gemm_f_kernel(float* __restrict__ out) {
    extern __shared__ __align__(16) char dsm[];
    char* base = (char*)(((uintptr_t)dsm + 1023) & ~(uintptr_t)1023);
    const uint32_t sb = s2u(base);

    const int tid  = threadIdx.x;
    const int lane = tid & 31;
    const int warp = tid >> 5;
    const int wm = warp & 1, wn = warp >> 1;
    const int gid = lane >> 2, tig = lane & 3;

    const int blk = blockIdx.y;
    const __half* A = g_att + (size_t)blockIdx.x * 128 * QKVROW + blk * INNER;
    const __half* B = g_wft + (size_t)blk * BLKD * INNER;
    float*        C = out + (size_t)blockIdx.x * 128 * DIMX + blk * BLKD;

#define LOAD_CHUNK(c, s)                                                           \
    do {                                                                           \
        const uint32_t st = sb + (uint32_t)(s) * (4 * SUB_BYTES);                  \
        load_sub_g(st,                 A + (c) * 64,      QKVROW, tid);            \
        load_sub_g(st + SUB_BYTES,     A + (c) * 64 + 32, QKVROW, tid);            \
        load_sub_g(st + 2 * SUB_BYTES, B + (c) * 64,      INNER, tid);             \
        load_sub_g(st + 3 * SUB_BYTES, B + (c) * 64 + 32, INNER, tid);             \
        cp_commit();                                                               \
    } while (0)

    FragCtx f;
    frag_init(f, lane, wm, wn);
    float acc[4][8][4];
#pragma unroll
    for (int mt = 0; mt < 4; mt++)
#pragma unroll
        for (int nt = 0; nt < 8; nt++)
#pragma unroll
            for (int e = 0; e < 4; e++) acc[mt][nt][e] = 0.f;

    LOAD_CHUNK(0, 0);

    for (int t = 0; t < 12; t++) {
        if (t + 1 < 12) { LOAD_CHUNK(t + 1, (t + 1) & 1); cp_wait<1>(); }
        else            { cp_wait<0>(); }
        __syncthreads();

        const uint32_t st = sb + (uint32_t)(t & 1) * (4 * SUB_BYTES);
        compute_k32(st,             st + 2 * SUB_BYTES, f, acc);
        compute_k32(st + SUB_BYTES, st + 3 * SUB_BYTES, f, acc);
        __syncthreads();
    }
#undef LOAD_CHUNK

    // staged fp32 epilogue: STS.64 -> rotated 64KB stage -> coalesced STG.128
#pragma unroll
    for (int mt = 0; mt < 4; mt++) {
#pragma unroll
        for (int nt = 0; nt < 8; nt++) {
            int r0  = wm * 64 + mt * 16 + gid;
            int u   = wn * 16 + nt * 2 + (tig >> 1);
            int off = (tig & 1) * 8;
            sts64(sb + FROT(r0, u) + off,     acc[mt][nt][0], acc[mt][nt][1]);
            sts64(sb + FROT(r0 + 8, u) + off, acc[mt][nt][2], acc[mt][nt][3]);
        }
    }
    __syncthreads();
#pragma unroll
    for (int p = 0; p < 32; p++) {
        int row = (tid >> 5) + p * 4;
        int u   = tid & 31;
        uint4 val;
        lds128(val, sb + FROT(row, u));
        *(uint4*)(C + (size_t)row * DIMX + u * 4) = val;
    }
}

// ---------------- attention: 1 CTA per token, 1 warp per head -----------------------
__global__ void __launch_bounds__(384) attn_kernel(float* __restrict__ smean) {
    const int t    = blockIdx.x;
    const int h    = threadIdx.x >> 5;
    const int lane = threadIdx.x & 31;

    __shared__ float sm[NHEAD][64];

    const size_t base = (size_t)t * QKVROW + h * HDIM;
    float2 q[8], k[8], v[8];
#pragma unroll
    for (int j = 0; j < 8; j++) {
        q[j] = __half22float2(((const __half2*)(g_q + base + j * INNER))[lane]);
        k[j] = __half22float2(((const __half2*)(g_k + base + j * INNER))[lane]);
        v[j] = __half22float2(((const __half2*)(g_v + base + j * INNER))[lane]);
    }

    // scores s(i,j) = dot64(q_i, k_j), f = i*8+j. Two passes of 32 sums each.
    float own0 = 0.f, own1 = 0.f;
#pragma unroll
    for (int hp = 0; hp < 2; hp++) {
        float cur[32];
#pragma unroll
        for (int fl = 0; fl < 32; fl++) {
            const int i = hp * 4 + (fl >> 3);
            const int j = fl & 7;
            cur[fl] = q[i].x * k[j].x + q[i].y * k[j].y;
        }
#pragma unroll
        for (int r = 0; r < 5; r++) {
            const int bit = (lane >> r) & 1;
#pragma unroll
            for (int x = 0; x < 16; x++) {
                if (x < (16 >> r)) {
                    float a0 = cur[2 * x], a1 = cur[2 * x + 1];
                    float keep = bit ? a1 : a0;
                    float send = bit ? a0 : a1;
                    float got = __shfl_xor_sync(0xFFFFFFFFu, send, 1 << r);
                    cur[x] = keep + got;
                }
            }
        }
        if (hp == 0) own0 = cur[0];
        else         own1 = cur[0];
    }
    own0 *= SCALE;
    own1 *= SCALE;

    // softmax over j within 8-lane groups
    float m0 = own0, m1 = own1;
#pragma unroll
    for (int m = 4; m >= 1; m >>= 1) {
        m0 = fmaxf(m0, __shfl_xor_sync(0xFFFFFFFFu, m0, m));
        m1 = fmaxf(m1, __shfl_xor_sync(0xFFFFFFFFu, m1, m));
    }
    float e0 = expf(own0 - m0), e1 = expf(own1 - m1);
    float s0 = e0, s1 = e1;
#pragma unroll
    for (int m = 4; m >= 1; m >>= 1) {
        s0 += __shfl_xor_sync(0xFFFFFFFFu, s0, m);
        s1 += __shfl_xor_sync(0xFFFFFFFFu, s1, m);
    }
    const float a0 = e0 / s0;
    const float a1 = e1 / s1;

    sm[h][lane]      = a0;
    sm[h][lane + 32] = a1;
    __syncwarp();

    // out_i = sum_j a(i,j) * v_j  (a via LDS broadcast)
    float2 acc[8];
#pragma unroll
    for (int i = 0; i < 8; i++) acc[i] = make_float2(0.f, 0.f);
#pragma unroll
    for (int i = 0; i < 8; i++) {
#pragma unroll
        for (int j = 0; j < 8; j++) {
            float aij = sm[h][i * 8 + j];
            acc[i].x = fmaf(aij, v[j].x, acc[i].x);
            acc[i].y = fmaf(aij, v[j].y, acc[i].y);
        }
    }
#pragma unroll
    for (int i = 0; i < 8; i++) {
        *(__half2*)(g_att + (size_t)t * QKVROW + i * INNER + h * HDIM + 2 * lane) =
            __floats2half2_rn(acc[i].x, acc[i].y);
    }

    __syncthreads();
    if (smean != nullptr && threadIdx.x < 64) {
        float s = 0.f;
#pragma unroll
        for (int hh = 0; hh < NHEAD; hh++) s += sm[hh][threadIdx.x];
        smean[(size_t)t * 64 + threadIdx.x] = s * (1.0f / 12.0f);
    }
}

// ---------------- launch ----------------
extern "C" void kernel_launch(void* const* d_in, const int* in_sizes, int n_in,
                              void* d_out, int out_size) {
    const float* x  = (const float*)d_in[0];
    const float* Wq = (const float*)d_in[1];
    const float* Wk = (const float*)d_in[2];
    const float* Wv = (const float*)d_in[3];
    const float* Wf = (const float*)d_in[4];
    float* out = (float*)d_out;

    cudaFuncSetAttribute(gemm_qkv_kernel, cudaFuncAttributeMaxDynamicSharedMemorySize, QKV_DSM);
    cudaFuncSetAttribute(gemm_f_kernel,   cudaFuncAttributeMaxDynamicSharedMemorySize, F_DSM);

    conv_x_kernel<<<SEQB * DIMX / 4 / 256, 256>>>(x);
    transpose_qkv_kernel<<<dim3(INNER / 32, BLKD / 32, 24), 256>>>(Wq, Wk, Wv);
    transpose_f_kernel<<<dim3(BLKD / 32, INNER / 32, NBLK), 256>>>(Wf);

    gemm_qkv_kernel<<<dim3(6, 32, 8), 256, QKV_DSM>>>();

    float* smean = (out_size >= SEQB * DIMX + SEQB * 64) ? (out + (size_t)SEQB * DIMX)
                                                         : nullptr;
    attn_kernel<<<SEQB, 384>>>(smean);

    gemm_f_kernel<<<dim3(32, NBLK), 128, F_DSM>>>(out);
}

// round 13
// speedup vs baseline: 1.0713x; 1.0713x over previous
#include <cuda_runtime.h>
#include <cuda_fp16.h>
#include <cstdint>

// Problem constants
#define SEQB   4096
#define DIMX   1024
#define NBLK   8
#define BLKD   128
#define NHEAD  12
#define HDIM   64
#define INNER  768
#define QKVROW (NBLK*INNER)        // 6144
#define WELEM  (NBLK*BLKD*INNER)   // 786432
#define SCALE  0.125f

// 128x32-half subtile (8KB), 64B rows, XOR-swizzled at 16B granularity
#define SUB_BYTES 8192
#define SWZ(row, ch) (((row) * 64) + ((((ch) ^ (((row) >> 1) & 3)) << 4)))

// fp32 epilogue stage layout (gemm_f)
#define FROT(row, u) (((row) * 512) + (((((u) + (row)) & 31)) << 4))   // fp32 tile, 64KB

#define QKV_DSM (12*SUB_BYTES + 1024)   // A(32KB) + 2 B buffers(64KB)
#define F_DSM   (8*SUB_BYTES + 1024)    // 2 stages x (2A + 2B); stage reuses all 64KB

// merged prep grid segmentation
#define PREP_CONV_BLOCKS  (SEQB*DIMX/4/256)              // 4096
#define PREP_TQKV_BLOCKS  ((INNER/32)*(BLKD/32)*24)      // 2304
#define PREP_TF_BLOCKS    ((BLKD/32)*(INNER/32)*NBLK)    // 768
#define PREP_BLOCKS       (PREP_CONV_BLOCKS + PREP_TQKV_BLOCKS + PREP_TF_BLOCKS)

// ---------------- scratch (device globals; allocation is forbidden) ----------------
__device__ __align__(16) __half g_xh [SEQB*DIMX];
__device__ __align__(16) __half g_wqt[WELEM];         // [blk][n=INNER][k=BLKD]
__device__ __align__(16) __half g_wkt[WELEM];
__device__ __align__(16) __half g_wvt[WELEM];
__device__ __align__(16) __half g_wft[WELEM];         // [blk][n=BLKD][k=INNER]
__device__ __align__(16) __half g_q  [SEQB*QKVROW];
__device__ __align__(16) __half g_k  [SEQB*QKVROW];
__device__ __align__(16) __half g_v  [SEQB*QKVROW];
__device__ __align__(16) __half g_att[SEQB*QKVROW];

// ---------------- helpers ----------------
__device__ __forceinline__ void mma_f16(float c[4], const uint32_t a[4],
                                        uint32_t b0, uint32_t b1) {
    asm volatile(
        "mma.sync.aligned.m16n8k16.row.col.f32.f16.f16.f32 "
        "{%0,%1,%2,%3}, {%4,%5,%6,%7}, {%8,%9}, {%0,%1,%2,%3};\n"
        : "+f"(c[0]), "+f"(c[1]), "+f"(c[2]), "+f"(c[3])
        : "r"(a[0]), "r"(a[1]), "r"(a[2]), "r"(a[3]), "r"(b0), "r"(b1));
}

__device__ __forceinline__ void ldsm4(uint32_t r[4], uint32_t addr) {
    asm volatile("ldmatrix.sync.aligned.m8n8.x4.shared.b16 {%0,%1,%2,%3}, [%4];"
                 : "=r"(r[0]), "=r"(r[1]), "=r"(r[2]), "=r"(r[3]) : "r"(addr));
}

__device__ __forceinline__ void stsm4(uint32_t addr, uint32_t v0, uint32_t v1,
                                      uint32_t v2, uint32_t v3) {
    asm volatile("stmatrix.sync.aligned.m8n8.x4.shared.b16 [%0], {%1,%2,%3,%4};"
                 :: "r"(addr), "r"(v0), "r"(v1), "r"(v2), "r"(v3) : "memory");
}

__device__ __forceinline__ void lds128(uint4& v, uint32_t addr) {
    asm volatile("ld.shared.v4.u32 {%0,%1,%2,%3}, [%4];"
                 : "=r"(v.x), "=r"(v.y), "=r"(v.z), "=r"(v.w) : "r"(addr));
}

__device__ __forceinline__ void sts64(uint32_t addr, float a, float b) {
    asm volatile("st.shared.v2.f32 [%0], {%1,%2};" :: "r"(addr), "f"(a), "f"(b) : "memory");
}

__device__ __forceinline__ uint32_t pack_h2(float a, float b) {
    __half2 h = __floats2half2_rn(a, b);
    return *(uint32_t*)&h;
}

__device__ __forceinline__ void cpa16(uint32_t smem_dst, const __half* gmem_src) {
    asm volatile("cp.async.ca.shared.global [%0], [%1], 16;\n" :: "r"(smem_dst), "l"(gmem_src));
}
__device__ __forceinline__ void cp_commit() { asm volatile("cp.async.commit_group;\n"); }
template <int N>
__device__ __forceinline__ void cp_wait() { asm volatile("cp.async.wait_group %0;\n" :: "n"(N)); }

__device__ __forceinline__ uint32_t s2u(const void* p) {
    return (uint32_t)__cvta_generic_to_shared(p);
}

// ---------------- merged prep: conv_x + transpose_qkv + transpose_f ---------------
__global__ void __launch_bounds__(256) prep_kernel(const float* __restrict__ x,
                                                   const float* __restrict__ wq,
                                                   const float* __restrict__ wk,
                                                   const float* __restrict__ wv,
                                                   const float* __restrict__ wf) {
    __shared__ float tile[32][33];
    const int bid = blockIdx.x;
    const int tid = threadIdx.x;

    if (bid < PREP_CONV_BLOCKS) {
        // x -> half
        int i = (bid * 256 + tid) * 4;
        float4 v = *(const float4*)(x + i);
        __half2* o = (__half2*)(g_xh + i);
        o[0] = __floats2half2_rn(v.x, v.y);
        o[1] = __floats2half2_rn(v.z, v.w);
        return;
    }

    int tx = tid & 31, ty0 = tid >> 5;

    if (bid < PREP_CONV_BLOCKS + PREP_TQKV_BLOCKS) {
        // transpose qkv weights: [k=BLKD][n=INNER] -> [n=INNER][k=BLKD] half
        int b2 = bid - PREP_CONV_BLOCKS;
        int bz = b2 / 96;                // 0..23 (mat*8 + blk)
        int rem = b2 % 96;
        int by = rem / 24;               // 0..3  k-tile
        int bx = rem % 24;               // 0..23 n-tile
        const int mat = bz >> 3;
        const int blk = bz & 7;
        const float* W = (mat == 0) ? wq : (mat == 1) ? wk : wv;
        __half* O      = (mat == 0) ? g_wqt : (mat == 1) ? g_wkt : g_wvt;
        const float* Wb = W + (size_t)blk * BLKD * INNER;
        __half* Ob      = O + (size_t)blk * BLKD * INNER;
        int n0 = bx * 32, k0 = by * 32;
#pragma unroll
        for (int p = 0; p < 4; p++) {
            int ty = ty0 + p * 8;
            tile[ty][tx] = Wb[(size_t)(k0 + ty) * INNER + n0 + tx];
        }
        __syncthreads();
#pragma unroll
        for (int p = 0; p < 4; p++) {
            int ty = ty0 + p * 8;
            Ob[(size_t)(n0 + ty) * BLKD + k0 + tx] = __float2half_rn(tile[tx][ty]);
        }
        return;
    }

    // transpose f weights: [k=INNER][n=BLKD] -> [n=BLKD][k=INNER] half
    int b3 = bid - PREP_CONV_BLOCKS - PREP_TQKV_BLOCKS;
    int bz = b3 / 96;                    // 0..7 blk
    int rem = b3 % 96;
    int by = rem / 4;                    // 0..23 k-tile
    int bx = rem % 4;                    // 0..3  n-tile
    const float* Wb = wf + (size_t)bz * INNER * BLKD;
    __half* Ob      = g_wft + (size_t)bz * INNER * BLKD;
    int n0 = bx * 32, k0 = by * 32;
#pragma unroll
    for (int p = 0; p < 4; p++) {
        int ty = ty0 + p * 8;
        tile[ty][tx] = Wb[(size_t)(k0 + ty) * BLKD + n0 + tx];
    }
    __syncthreads();
#pragma unroll
    for (int p = 0; p < 4; p++) {
        int ty = ty0 + p * 8;
        Ob[(size_t)(n0 + ty) * INNER + k0 + tx] = __float2half_rn(tile[tx][ty]);
    }
}

// ---------------- mma core: warp tile 64(M) x 64(N), CTA 128x128, 4 warps ---------
struct FragCtx {
    int a_row[4];
    int b_row[4];
    int ac, bc;
};

__device__ __forceinline__ void frag_init(FragCtx& f, int lane, int wm, int wn) {
#pragma unroll
    for (int mt = 0; mt < 4; mt++)
        f.a_row[mt] = wm * 64 + mt * 16 + (lane & 7) + ((lane >> 3) & 1) * 8;
#pragma unroll
    for (int np = 0; np < 4; np++)
        f.b_row[np] = wn * 64 + np * 16 + (lane & 7) + ((lane >> 4) & 1) * 8;
    f.ac = lane >> 4;
    f.bc = (lane >> 3) & 1;
}

__device__ __forceinline__ void compute_k32(uint32_t ab, uint32_t bb, const FragCtx& f,
                                            float acc[4][8][4]) {
#pragma unroll
    for (int ks = 0; ks < 2; ks++) {
        const int kb = ks * 2;
        uint32_t a[4][4];
#pragma unroll
        for (int mt = 0; mt < 4; mt++)
            ldsm4(a[mt], ab + SWZ(f.a_row[mt], kb + f.ac));
        uint32_t bf[4][4];
#pragma unroll
        for (int np = 0; np < 4; np++)
            ldsm4(bf[np], bb + SWZ(f.b_row[np], kb + f.bc));
#pragma unroll
        for (int mt = 0; mt < 4; mt++) {
#pragma unroll
            for (int np = 0; np < 4; np++) {
                mma_f16(acc[mt][np * 2 + 0], a[mt], bf[np][0], bf[np][1]);
                mma_f16(acc[mt][np * 2 + 1], a[mt], bf[np][2], bf[np][3]);
            }
        }
    }
}

// load one 128x32 subtile (row-major src, row stride ld halves); 128 threads, 4 cp each
__device__ __forceinline__ void load_sub(uint32_t dst, const __half* __restrict__ src, int ld) {
    const int r0 = threadIdx.x >> 2, c = threadIdx.x & 3;
#pragma unroll
    for (int p = 0; p < 4; p++) {
        const int r = r0 + p * 32;
        cpa16(dst + SWZ(r, c), src + (size_t)r * ld + c * 8);
    }
}

// warp-local subtile load: one warp covers a whole 128x32 subtile (16 cp per lane)
__device__ __forceinline__ void load_sub_warp(uint32_t dst, const __half* __restrict__ src,
                                              int ld, int lane) {
    const int r0 = lane >> 2, c = lane & 3;
#pragma unroll
    for (int p = 0; p < 16; p++) {
        const int r = r0 + p * 8;
        cpa16(dst + SWZ(r, c), src + (size_t)r * ld + c * 8);
    }
}

// ---------------- per-warp half epilogue: stmatrix -> own 8KB region -> STG.128 ----
__device__ __forceinline__ void warp_epi_half(const float acc[4][8][4],
                                              __half* __restrict__ C, int ldc,
                                              uint32_t region, int wm, int wn, int lane) {
    const int t4 = lane >> 3, rr = lane & 7;
#pragma unroll
    for (int mt = 0; mt < 4; mt++) {
#pragma unroll
        for (int ntp = 0; ntp < 4; ntp++) {
            int lr = mt * 16 + (t4 & 1) * 8 + rr;
            int u  = ntp * 2 + (t4 >> 1);
            uint32_t v0 = pack_h2(acc[mt][2 * ntp][0],     acc[mt][2 * ntp][1]);
            uint32_t v1 = pack_h2(acc[mt][2 * ntp][2],     acc[mt][2 * ntp][3]);
            uint32_t v2 = pack_h2(acc[mt][2 * ntp + 1][0], acc[mt][2 * ntp + 1][1]);
            uint32_t v3 = pack_h2(acc[mt][2 * ntp + 1][2], acc[mt][2 * ntp + 1][3]);
            stsm4(region + lr * 128 + (((u + lr) & 7) << 4), v0, v1, v2, v3);
        }
    }
    __syncwarp();
#pragma unroll
    for (int p = 0; p < 16; p++) {
        int lr = p * 4 + (lane >> 3);
        int u  = lane & 7;
        uint4 val;
        lds128(val, region + lr * 128 + (((u + lr) & 7) << 4));
        *(uint4*)(C + (size_t)(wm * 64 + lr) * ldc + wn * 64 + u * 8) = val;
    }
}

// ---------------- QKV: fused q/k/v, per-warp epilogues. grid (6, 32, 8) ------------
__global__ void __launch_bounds__(128, 2) gemm_qkv_kernel() {
    extern __shared__ __align__(16) char dsm[];
    char* base = (char*)(((uintptr_t)dsm + 1023) & ~(uintptr_t)1023);
    const uint32_t Asb = s2u(base);
    const uint32_t Bsb0 = Asb + 4 * SUB_BYTES;
    const uint32_t Bsb1 = Asb + 8 * SUB_BYTES;

    const int tid  = threadIdx.x;
    const int lane = tid & 31;
    const int warp = tid >> 5;
    const int wm = warp & 1, wn = warp >> 1;

    const int blk = blockIdx.z;
    const size_t woff = (size_t)blk * BLKD * INNER + (size_t)blockIdx.x * 128 * BLKD;
    const size_t coff = (size_t)blockIdx.y * 128 * QKVROW + blk * INNER + blockIdx.x * 128;
    const __half* A  = g_xh + (size_t)blockIdx.y * 128 * DIMX + blk * BLKD;
    const __half* Bq = g_wqt + woff;
    const __half* Bk = g_wkt + woff;
    const __half* Bv = g_wvt + woff;
    __half* Cq = g_q + coff;
    __half* Ck = g_k + coff;
    __half* Cv = g_v + coff;

    const uint32_t reg0 = Bsb0 + (uint32_t)warp * SUB_BYTES;   // warp's stage in B0
    const uint32_t reg1 = Bsb1 + (uint32_t)warp * SUB_BYTES;   // warp's stage in B1

    // group1: A + B(q); group2: B(k)
#pragma unroll
    for (int t = 0; t < 4; t++) {
        load_sub(Asb + t * SUB_BYTES,  A  + t * 32, DIMX);
        load_sub(Bsb0 + t * SUB_BYTES, Bq + t * 32, BLKD);
    }
    cp_commit();
#pragma unroll
    for (int t = 0; t < 4; t++)
        load_sub(Bsb1 + t * SUB_BYTES, Bk + t * 32, BLKD);
    cp_commit();

    FragCtx f;
    frag_init(f, lane, wm, wn);
    float acc[4][8][4];

    // ---- q ----
#pragma unroll
    for (int mt = 0; mt < 4; mt++)
#pragma unroll
        for (int nt = 0; nt < 8; nt++)
#pragma unroll
            for (int e = 0; e < 4; e++) acc[mt][nt][e] = 0.f;
    cp_wait<1>();           // group1 (A, Bq) complete
    __syncthreads();
#pragma unroll
    for (int t = 0; t < 4; t++)
        compute_k32(Asb + t * SUB_BYTES, Bsb0 + t * SUB_BYTES, f, acc);
    __syncthreads();        // all warps done reading B0 -> B0 usable as stage
    warp_epi_half(acc, Cq, QKVROW, reg0, wm, wn, lane);
    // group3: warp refills ITS OWN drained region with its Bv subtile
    load_sub_warp(reg0, Bv + warp * 32, BLKD, lane);
    cp_commit();

    // ---- k ----
#pragma unroll
    for (int mt = 0; mt < 4; mt++)
#pragma unroll
        for (int nt = 0; nt < 8; nt++)
#pragma unroll
            for (int e = 0; e < 4; e++) acc[mt][nt][e] = 0.f;
    cp_wait<1>();           // group2 (Bk) complete
    __syncthreads();
#pragma unroll
    for (int t = 0; t < 4; t++)
        compute_k32(Asb + t * SUB_BYTES, Bsb1 + t * SUB_BYTES, f, acc);
    __syncthreads();        // all warps done reading B1 -> B1 usable as stage
    warp_epi_half(acc, Ck, QKVROW, reg1, wm, wn, lane);

    // ---- v ----
#pragma unroll
    for (int mt = 0; mt < 4; mt++)
#pragma unroll
        for (int nt = 0; nt < 8; nt++)
#pragma unroll
            for (int e = 0; e < 4; e++) acc[mt][nt][e] = 0.f;
    cp_wait<0>();           // all Bv subtiles complete
    __syncthreads();
#pragma unroll
    for (int t = 0; t < 4; t++)
        compute_k32(Asb + t * SUB_BYTES, Bsb0 + t * SUB_BYTES, f, acc);
    warp_epi_half(acc, Cv, QKVROW, reg1, wm, wn, lane);
}

// ---------------- output projection: K=768 as 12 k64 chunks, 2-stage ring ----------
__global__ void __launch_bounds__(128, 2) gemm_f_kernel(float* __restrict__ out) {
    extern __shared__ __align__(16) char dsm[];
    char* base = (char*)(((uintptr_t)dsm + 1023) & ~(uintptr_t)1023);
    const uint32_t sb = s2u(base);

    const int tid  = threadIdx.x;
    const int lane = tid & 31;
    const int warp = tid >> 5;
    const int wm = warp & 1, wn = warp >> 1;
    const int gid = lane >> 2, tig = lane & 3;

    const int blk = blockIdx.y;
    const __half* A = g_att + (size_t)blockIdx.x * 128 * QKVROW + blk * INNER;
    const __half* B = g_wft + (size_t)blk * BLKD * INNER;
    float*        C = out + (size_t)blockIdx.x * 128 * DIMX + blk * BLKD;

#define LOAD_CHUNK(c, s)                                                           \
    do {                                                                           \
        const uint32_t st = sb + (uint32_t)(s) * (4 * SUB_BYTES);                  \
        load_sub(st,                 A + (c) * 64,      QKVROW);                   \
        load_sub(st + SUB_BYTES,     A + (c) * 64 + 32, QKVROW);                   \
        load_sub(st + 2 * SUB_BYTES, B + (c) * 64,      INNER);                    \
        load_sub(st + 3 * SUB_BYTES, B + (c) * 64 + 32, INNER);                    \
        cp_commit();                                                               \
    } while (0)

    FragCtx f;
    frag_init(f, lane, wm, wn);
    float acc[4][8][4];
#pragma unroll
    for (int mt = 0; mt < 4; mt++)
#pragma unroll
        for (int nt = 0; nt < 8; nt++)
#pragma unroll
            for (int e = 0; e < 4; e++) acc[mt][nt][e] = 0.f;

    LOAD_CHUNK(0, 0);

    for (int t = 0; t < 12; t++) {
        if (t + 1 < 12) { LOAD_CHUNK(t + 1, (t + 1) & 1); cp_wait<1>(); }
        else            { cp_wait<0>(); }
        __syncthreads();

        const uint32_t st = sb + (uint32_t)(t & 1) * (4 * SUB_BYTES);
        compute_k32(st,             st + 2 * SUB_BYTES, f, acc);
        compute_k32(st + SUB_BYTES, st + 3 * SUB_BYTES, f, acc);
        __syncthreads();
    }
#undef LOAD_CHUNK

    // staged fp32 epilogue: STS.64 -> rotated 64KB stage -> coalesced STG.128
#pragma unroll
    for (int mt = 0; mt < 4; mt++) {
#pragma unroll
        for (int nt = 0; nt < 8; nt++) {
            int r0  = wm * 64 + mt * 16 + gid;
            int u   = wn * 16 + nt * 2 + (tig >> 1);
            int off = (tig & 1) * 8;
            sts64(sb + FROT(r0, u) + off,     acc[mt][nt][0], acc[mt][nt][1]);
            sts64(sb + FROT(r0 + 8, u) + off, acc[mt][nt][2], acc[mt][nt][3]);
        }
    }
    __syncthreads();
#pragma unroll
    for (int p = 0; p < 32; p++) {
        int row = (tid >> 5) + p * 4;
        int u   = tid & 31;
        uint4 val;
        lds128(val, sb + FROT(row, u));
        *(uint4*)(C + (size_t)row * DIMX + u * 4) = val;
    }
}

// ---------------- attention: 1 CTA per token, 1 warp per head -----------------------
__global__ void __launch_bounds__(384) attn_kernel(float* __restrict__ smean) {
    const int t    = blockIdx.x;
    const int h    = threadIdx.x >> 5;
    const int lane = threadIdx.x & 31;

    __shared__ float sm[NHEAD][64];

    const size_t base = (size_t)t * QKVROW + h * HDIM;
    float2 q[8], k[8], v[8];
#pragma unroll
    for (int j = 0; j < 8; j++) {
        q[j] = __half22float2(((const __half2*)(g_q + base + j * INNER))[lane]);
        k[j] = __half22float2(((const __half2*)(g_k + base + j * INNER))[lane]);
        v[j] = __half22float2(((const __half2*)(g_v + base + j * INNER))[lane]);
    }

    // scores s(i,j) = dot64(q_i, k_j), f = i*8+j. Two passes of 32 sums each.
    float own0 = 0.f, own1 = 0.f;
#pragma unroll
    for (int hp = 0; hp < 2; hp++) {
        float cur[32];
#pragma unroll
        for (int fl = 0; fl < 32; fl++) {
            const int i = hp * 4 + (fl >> 3);
            const int j = fl & 7;
            cur[fl] = q[i].x * k[j].x + q[i].y * k[j].y;
        }
#pragma unroll
        for (int r = 0; r < 5; r++) {
            const int bit = (lane >> r) & 1;
#pragma unroll
            for (int x = 0; x < 16; x++) {
                if (x < (16 >> r)) {
                    float a0 = cur[2 * x], a1 = cur[2 * x + 1];
                    float keep = bit ? a1 : a0;
                    float send = bit ? a0 : a1;
                    float got = __shfl_xor_sync(0xFFFFFFFFu, send, 1 << r);
                    cur[x] = keep + got;
                }
            }
        }
        if (hp == 0) own0 = cur[0];
        else         own1 = cur[0];
    }
    own0 *= SCALE;
    own1 *= SCALE;

    // softmax over j within 8-lane groups
    float m0 = own0, m1 = own1;
#pragma unroll
    for (int m = 4; m >= 1; m >>= 1) {
        m0 = fmaxf(m0, __shfl_xor_sync(0xFFFFFFFFu, m0, m));
        m1 = fmaxf(m1, __shfl_xor_sync(0xFFFFFFFFu, m1, m));
    }
    float e0 = expf(own0 - m0), e1 = expf(own1 - m1);
    float s0 = e0, s1 = e1;
#pragma unroll
    for (int m = 4; m >= 1; m >>= 1) {
        s0 += __shfl_xor_sync(0xFFFFFFFFu, s0, m);
        s1 += __shfl_xor_sync(0xFFFFFFFFu, s1, m);
    }
    const float a0 = e0 / s0;
    const float a1 = e1 / s1;

    sm[h][lane]      = a0;
    sm[h][lane + 32] = a1;
    __syncwarp();

    // out_i = sum_j a(i,j) * v_j  (a via LDS broadcast)
    float2 acc[8];
#pragma unroll
    for (int i = 0; i < 8; i++) acc[i] = make_float2(0.f, 0.f);
#pragma unroll
    for (int i = 0; i < 8; i++) {
#pragma unroll
        for (int j = 0; j < 8; j++) {
            float aij = sm[h][i * 8 + j];
            acc[i].x = fmaf(aij, v[j].x, acc[i].x);
            acc[i].y = fmaf(aij, v[j].y, acc[i].y);
        }
    }
#pragma unroll
    for (int i = 0; i < 8; i++) {
        *(__half2*)(g_att + (size_t)t * QKVROW + i * INNER + h * HDIM + 2 * lane) =
            __floats2half2_rn(acc[i].x, acc[i].y);
    }

    __syncthreads();
    if (smean != nullptr && threadIdx.x < 64) {
        float s = 0.f;
#pragma unroll
        for (int hh = 0; hh < NHEAD; hh++) s += sm[hh][threadIdx.x];
        smean[(size_t)t * 64 + threadIdx.x] = s * (1.0f / 12.0f);
    }
}

// ---------------- launch ----------------
extern "C" void kernel_launch(void* const* d_in, const int* in_sizes, int n_in,
                              void* d_out, int out_size) {
    const float* x  = (const float*)d_in[0];
    const float* Wq = (const float*)d_in[1];
    const float* Wk = (const float*)d_in[2];
    const float* Wv = (const float*)d_in[3];
    const float* Wf = (const float*)d_in[4];
    float* out = (float*)d_out;

    cudaFuncSetAttribute(gemm_qkv_kernel, cudaFuncAttributeMaxDynamicSharedMemorySize, QKV_DSM);
    cudaFuncSetAttribute(gemm_f_kernel,   cudaFuncAttributeMaxDynamicSharedMemorySize, F_DSM);

    prep_kernel<<<PREP_BLOCKS, 256>>>(x, Wq, Wk, Wv, Wf);

    gemm_qkv_kernel<<<dim3(6, 32, 8), 128, QKV_DSM>>>();

    float* smean = (out_size >= SEQB * DIMX + SEQB * 64) ? (out + (size_t)SEQB * DIMX)
                                                         : nullptr;
    attn_kernel<<<SEQB, 384>>>(smean);

    gemm_f_kernel<<<dim3(32, NBLK), 128, F_DSM>>>(out);
}